// round 17
// baseline (speedup 1.0000x reference)
#include <cuda_runtime.h>
#include <cuda_bf16.h>

#define T_DIM 1024
#define B_DIM 64
#define H_DIM 1024
#define NSPL 32                   // o-splits (32 o each) -> partials 8 MB
#define OO 32                     // o per split (2 halves of 16)
#define BB 4                      // b per k1 CTA
#define K1_NCTA 1024              // k1 compute CTAs
#define NRED 64                   // finisher-reducer CTAs (last 64 tickets)
#define TPW 8                     // t-rows per warp in kB (R8 winner)
#define CHUNKS_PER_B (T_DIM / (8 * TPW))   // 16

// Scratch (allocation-free rule: __device__ globals; zero-initialized)
__device__ float g_partial[NSPL * B_DIM * H_DIM];    // 8 MB: [s][b][h]
__device__ float g_v[B_DIM * H_DIM];                 // 256 KB
__device__ float g_energies[B_DIM * T_DIM];          // 256 KB: [b][t]
__device__ unsigned g_k1_done;                       // k1 finish tickets
__device__ unsigned g_red_done;                      // reducer arrivals
__device__ unsigned g_cnt[B_DIM];                    // kB per-b arrivals
__device__ unsigned g_sm_done;                       // kB softmax arrivals

// ---------------------------------------------------------------------------
// kA: proj partials + v-reduction fused via finisher-tail.
// Compute: thread owns float4-of-h x 4 b's; two w4[16] halves (o0..o0+31)
// accumulate into acc[4] -> one 32-o partial per (b,h4). 1024 CTAs.
// Tail: ticket AFTER stores; last 64 finishers reduce 1/64 of v each.
// Deadlock-free: tickets are post-compute, so spinners' SMs are already
// drained of work; queued CTAs always have slots.
// ---------------------------------------------------------------------------
__global__ void __launch_bounds__(128) kA_proj(
    const float* __restrict__ hid, const float* __restrict__ W)
{
    const int h0 = (blockIdx.x * 128 + threadIdx.x) * 4;   // float4 of h
    const int o0 = blockIdx.y * OO;
    const int b0 = blockIdx.z * BB;

    __shared__ float sh[BB * OO];   // 512 B
    for (int i = threadIdx.x; i < BB * OO; i += 128) {
        int bb = i / OO;
        int oo = i % OO;
        sh[i] = hid[(b0 + bb) * H_DIM + o0 + oo];
    }
    __syncthreads();

    float4 acc[BB];
#pragma unroll
    for (int bb = 0; bb < BB; bb++)
        acc[bb] = make_float4(0.f, 0.f, 0.f, 0.f);

#pragma unroll
    for (int half = 0; half < 2; half++) {
        float4 w4[16];
#pragma unroll
        for (int oo = 0; oo < 16; oo++)
            w4[oo] = *reinterpret_cast<const float4*>(
                W + (size_t)(o0 + half * 16 + oo) * H_DIM + h0);

#pragma unroll
        for (int bb = 0; bb < BB; bb++) {
            const float4* s4 = reinterpret_cast<const float4*>(
                sh + bb * OO + half * 16);
            float4 hv0 = s4[0], hv1 = s4[1], hv2 = s4[2], hv3 = s4[3];
#define FMA4(hs, oo)                                                       \
            acc[bb].x += (hs) * w4[oo].x; acc[bb].y += (hs) * w4[oo].y;    \
            acc[bb].z += (hs) * w4[oo].z; acc[bb].w += (hs) * w4[oo].w;
            FMA4(hv0.x, 0)  FMA4(hv0.y, 1)  FMA4(hv0.z, 2)  FMA4(hv0.w, 3)
            FMA4(hv1.x, 4)  FMA4(hv1.y, 5)  FMA4(hv1.z, 6)  FMA4(hv1.w, 7)
            FMA4(hv2.x, 8)  FMA4(hv2.y, 9)  FMA4(hv2.z, 10) FMA4(hv2.w, 11)
            FMA4(hv3.x, 12) FMA4(hv3.y, 13) FMA4(hv3.z, 14) FMA4(hv3.w, 15)
#undef FMA4
        }
    }

    float4* part = reinterpret_cast<float4*>(
        g_partial + (size_t)blockIdx.y * (B_DIM * H_DIM) + h0);
#pragma unroll
    for (int bb = 0; bb < BB; bb++)
        part[(size_t)(b0 + bb) * (H_DIM / 4)] = acc[bb];

    // ---- finisher-tail ----
    __threadfence();                 // publish partials
    __syncthreads();
    __shared__ unsigned s_ticket;
    if (threadIdx.x == 0)
        s_ticket = atomicAdd(&g_k1_done, 1u);
    __syncthreads();
    const unsigned ticket = s_ticket;
    if (ticket < K1_NCTA - NRED)
        return;                      // not among last 64 finishers

    if (threadIdx.x == 0) {
        while (atomicAdd(&g_k1_done, 0u) < K1_NCTA)
            __nanosleep(64);
    }
    __syncthreads();
    __threadfence();                 // acquire all partials

    // reducer r handles 256 float4 of v (2 per thread)
    const int r = (int)(ticket - (K1_NCTA - NRED));
    const float4* gp4 = reinterpret_cast<const float4*>(g_partial);
    float4* gv4 = reinterpret_cast<float4*>(g_v);

#pragma unroll
    for (int e = 0; e < 2; e++) {
        const int i4 = r * 256 + threadIdx.x + e * 128;
        float4 s0 = make_float4(0.f, 0.f, 0.f, 0.f);
        float4 s1 = make_float4(0.f, 0.f, 0.f, 0.f);
        float4 s2 = make_float4(0.f, 0.f, 0.f, 0.f);
        float4 s3 = make_float4(0.f, 0.f, 0.f, 0.f);
#pragma unroll
        for (int p = 0; p < NSPL; p += 4) {
            float4 x0 = gp4[(size_t)(p + 0) * (B_DIM * H_DIM / 4) + i4];
            float4 x1 = gp4[(size_t)(p + 1) * (B_DIM * H_DIM / 4) + i4];
            float4 x2 = gp4[(size_t)(p + 2) * (B_DIM * H_DIM / 4) + i4];
            float4 x3 = gp4[(size_t)(p + 3) * (B_DIM * H_DIM / 4) + i4];
            s0.x += x0.x; s0.y += x0.y; s0.z += x0.z; s0.w += x0.w;
            s1.x += x1.x; s1.y += x1.y; s1.z += x1.z; s1.w += x1.w;
            s2.x += x2.x; s2.y += x2.y; s2.z += x2.z; s2.w += x2.w;
            s3.x += x3.x; s3.y += x3.y; s3.z += x3.z; s3.w += x3.w;
        }
        float4 o;
        o.x = (s0.x + s1.x) + (s2.x + s3.x);
        o.y = (s0.y + s1.y) + (s2.y + s3.y);
        o.z = (s0.z + s1.z) + (s2.z + s3.z);
        o.w = (s0.w + s1.w) + (s2.w + s3.w);
        gv4[i4] = o;
    }

    // last reducer resets phase-A counters for the next graph replay
    __threadfence();
    __syncthreads();
    if (threadIdx.x == 0) {
        unsigned old = atomicAdd(&g_red_done, 1u);
        if (old == NRED - 1) {
            g_k1_done = 0u;
            g_red_done = 0u;
        }
    }
}

// ---------------------------------------------------------------------------
// kB: k2 (energies) + k3 (softmax) in ONE launch (R13/R14 proven: 47.1us,
// DRAM=73%). y<16: R8 k2 CTA + arrival. y==16 (last 64 bids): per-b softmax
// CTA spins for its 16 producers, then 256 thr x float4 softmax.
// Last softmax CTA resets counters for the next graph replay.
// Bias dropped (softmax shift invariance).
// ---------------------------------------------------------------------------
__global__ void __launch_bounds__(256) kB_energies_softmax(
    const float* __restrict__ enc, float* __restrict__ out)
{
    const int warp = threadIdx.x >> 5;
    const int lane = threadIdx.x & 31;
    const int b    = blockIdx.x;                       // 0..63

    if (blockIdx.y < CHUNKS_PER_B) {
        // ---- k2 compute (R8 body) ----
        const int t0 = blockIdx.y * (8 * TPW) + warp * TPW;

        const float4* v4 = reinterpret_cast<const float4*>(g_v + b * H_DIM);
        float4 v[8];
#pragma unroll
        for (int k = 0; k < 8; k++)
            v[k] = v4[lane + 32 * k];

        const float4* e4 = reinterpret_cast<const float4*>(
            enc + (size_t)(t0 * B_DIM + b) * H_DIM) + lane;
        const size_t row_stride4 = (size_t)B_DIM * H_DIM / 4;

        float* eout = g_energies + b * T_DIM + t0;

#pragma unroll 4
        for (int i = 0; i < TPW; i++) {
            float acc = 0.f;
#pragma unroll
            for (int k = 0; k < 8; k++) {
                float4 x = __ldcs(e4 + 32 * k);
                acc += x.x * v[k].x + x.y * v[k].y + x.z * v[k].z + x.w * v[k].w;
            }
#pragma unroll
            for (int off = 16; off; off >>= 1)
                acc += __shfl_xor_sync(0xffffffffu, acc, off);
            if (lane == 0)
                eout[i] = acc;
            e4 += row_stride4;
        }

        // release: publish energies, then arrive on this b's counter
        __threadfence();
        __syncthreads();
        if (threadIdx.x == 0)
            atomicAdd(&g_cnt[b], 1u);
        return;
    }

    // ---- softmax CTA for row b ----
    if (threadIdx.x == 0) {
        while (atomicAdd(&g_cnt[b], 0u) < CHUNKS_PER_B)
            __nanosleep(64);
    }
    __syncthreads();
    __threadfence();     // acquire: see all 16 producers' energy stores

    const int tid = threadIdx.x;
    __shared__ float sred[8];

    float4 x = reinterpret_cast<const float4*>(g_energies + b * T_DIM)[tid];

    float m = fmaxf(fmaxf(x.x, x.y), fmaxf(x.z, x.w));
#pragma unroll
    for (int off = 16; off; off >>= 1)
        m = fmaxf(m, __shfl_xor_sync(0xffffffffu, m, off));
    if (lane == 0) sred[warp] = m;
    __syncthreads();
    m = sred[0];
#pragma unroll
    for (int w2 = 1; w2 < 8; w2++)
        m = fmaxf(m, sred[w2]);
    __syncthreads();

    x.x = __expf(x.x - m);
    x.y = __expf(x.y - m);
    x.z = __expf(x.z - m);
    x.w = __expf(x.w - m);
    float lsum = x.x + x.y + x.z + x.w;
#pragma unroll
    for (int off = 16; off; off >>= 1)
        lsum += __shfl_xor_sync(0xffffffffu, lsum, off);
    if (lane == 0) sred[warp] = lsum;
    __syncthreads();
    float tot = 0.f;
#pragma unroll
    for (int w2 = 0; w2 < 8; w2++)
        tot += sred[w2];
    const float inv = 1.f / tot;

    x.x *= inv; x.y *= inv; x.z *= inv; x.w *= inv;
    reinterpret_cast<float4*>(out + b * T_DIM)[tid] = x;

    // last softmax CTA resets counters for the next replay
    __threadfence();
    __syncthreads();
    if (threadIdx.x == 0) {
        unsigned old = atomicAdd(&g_sm_done, 1u);
        if (old == B_DIM - 1) {
            for (int i = 0; i < B_DIM; i++)
                g_cnt[i] = 0u;
            g_sm_done = 0u;
        }
    }
}

// ---------------------------------------------------------------------------
extern "C" void kernel_launch(void* const* d_in, const int* in_sizes, int n_in,
                              void* d_out, int out_size)
{
    const float* hid = (const float*)d_in[0];   // [1, B, H]
    const float* enc = (const float*)d_in[1];   // [T, B, H]
    const float* W   = (const float*)d_in[2];   // [H, H]
    // d_in[3] = bias: dropped — softmax shift-invariance makes it a no-op.
    float* out = (float*)d_out;                 // [B, 1, T]

    kA_proj<<<dim3(H_DIM / 512, NSPL, B_DIM / BB), 128>>>(hid, W);
    kB_energies_softmax<<<dim3(B_DIM, CHUNKS_PER_B + 1), 256>>>(enc, out);
}